// round 17
// baseline (speedup 1.0000x reference)
#include <cuda_runtime.h>
#include <cuda_fp16.h>
#include <cstdint>

// GNN_82592221102580 — fused per 64x64 batch tile (nc = 4096):
//   E = exp(X); Sinv[i] = 1/sum_k E[k][i]
//   Xn = LayerNorm(X) (ddof=1)
//   node_u = E^T @ Xn                 <- mma.m16n8k16 fp16 (f32 acc), UNSCALED
//   out    = diag(Sinv) relu(node_u @ W)   (scaling deferred past relu: Sinv>0)
//
// PERSISTENT: 592 CTAs loop over tile-pairs; W/a2/b2 staged once per CTA.
// 256 thr/CTA; warps 0-3 own tile0 of the pair end-to-end, warps 4-7 tile1
// (named barriers per half). Operands half2-packed in XOR-swizzled buffers,
// fragment loads via ldmatrix.m8n8.x4.

__device__ __forceinline__ int swz(int i, int kp) {          // word index
    return i * 32 + (kp ^ ((((i >> 3) ^ i) & 7) << 2));
}
__device__ __forceinline__ int swzb(int row, int kp) {       // byte offset
    return row * 128 + 4 * (kp ^ ((((row >> 3) ^ row) & 7) << 2));
}

// pack (lo, hi) -> u32, lo in bits[15:0]. PTX cvt.rn.f16x2.f32 d,a,b puts b low.
__device__ __forceinline__ uint32_t pack_h2(float lo, float hi) {
    uint32_t r;
    asm("cvt.rn.f16x2.f32 %0, %1, %2;" : "=r"(r) : "f"(hi), "f"(lo));
    return r;
}

__device__ __forceinline__ void ldm_x4(uint32_t& r0, uint32_t& r1, uint32_t& r2,
                                       uint32_t& r3, uint32_t addr) {
    asm volatile("ldmatrix.sync.aligned.m8n8.x4.shared.b16 {%0,%1,%2,%3}, [%4];"
                 : "=r"(r0), "=r"(r1), "=r"(r2), "=r"(r3) : "r"(addr));
}

__device__ __forceinline__ void mma_f16(float d[4], const uint32_t a[4],
                                        uint32_t b0, uint32_t b1) {
    asm volatile(
        "mma.sync.aligned.m16n8k16.row.col.f32.f16.f16.f32 "
        "{%0,%1,%2,%3}, {%4,%5,%6,%7}, {%8,%9}, {%0,%1,%2,%3};"
        : "+f"(d[0]), "+f"(d[1]), "+f"(d[2]), "+f"(d[3])
        : "r"(a[0]), "r"(a[1]), "r"(a[2]), "r"(a[3]), "r"(b0), "r"(b1));
}

#define BAR_HALF(h) asm volatile("bar.sync %0, 128;" :: "r"(1 + (h)) : "memory")

// dynamic smem layout (bytes)
#define OF_ET 0          // [2][2048] u32  ET packed; ND overlays after GEMM1
#define OF_XN 16384      // [2][2048] u32  Xn^T packed
#define OF_WT 32768      // [2048]    u32  W^T packed
#define OF_SP 40960      // [2][4][64] f32 colsum partials
#define OF_SI 43008      // [2][64]   f32  Sinv
#define OF_A2 43520      // [64] f32
#define OF_B2 43776      // [64] f32
#define SMEM_BYTES 44032

__global__ __launch_bounds__(256, 4) void gnn_fused_kernel(
    const float* __restrict__ X,
    const float* __restrict__ W,
    const float* __restrict__ a2,
    const float* __restrict__ b2,
    float* __restrict__ out,
    int nPairs)
{
    extern __shared__ __align__(16) char sm[];
    uint32_t* ET = (uint32_t*)(sm + OF_ET);
    uint32_t* XN = (uint32_t*)(sm + OF_XN);
    uint32_t* WT = (uint32_t*)(sm + OF_WT);
    float*    Sp = (float*)(sm + OF_SP);
    float*    Si = (float*)(sm + OF_SI);
    float*   a2s = (float*)(sm + OF_A2);
    float*   b2s = (float*)(sm + OF_B2);

    const uint32_t smb = (uint32_t)__cvta_generic_to_shared(sm);

    const int t    = threadIdx.x;
    const int warp = t >> 5;
    const int lane = t & 31;
    const int h    = warp >> 2;    // tile of the pair owned by this warp group
    const int wt   = t & 127;      // thread-in-half
    const int ww   = warp & 3;     // warp-in-half

    if (t < 64) { a2s[t] = a2[t]; b2s[t] = b2[t]; }

    // ---- one-time W -> WT staging (all 256 threads) ----
    {
        const int R = t >> 3;      // row-pair 0..31
        const int C = t & 7;
        float w0[8], w1[8];
        float4 v;
        v = *(const float4*)(W + (2*R)*64     + 4*C); w0[0]=v.x; w0[1]=v.y; w0[2]=v.z; w0[3]=v.w;
        v = *(const float4*)(W + (2*R)*64 +32 + 4*C); w0[4]=v.x; w0[5]=v.y; w0[6]=v.z; w0[7]=v.w;
        v = *(const float4*)(W + (2*R+1)*64   + 4*C); w1[0]=v.x; w1[1]=v.y; w1[2]=v.z; w1[3]=v.w;
        v = *(const float4*)(W + (2*R+1)*64+32+ 4*C); w1[4]=v.x; w1[5]=v.y; w1[6]=v.z; w1[7]=v.w;
#pragma unroll
        for (int q = 0; q < 8; q++) {
            const int c = 4*C + (q & 3) + (q >> 2) * 32;
            WT[swz(c, R)] = pack_h2(w0[q], w1[q]);
        }
    }
    __syncthreads();   // only full-CTA barrier

    // loop-invariant GEMM indexing
    const int C   = wt & 7;
    const int i0w = (ww & 1) * 32;
    const int j0w = (ww >> 1) * 32;
    const int g   = lane >> 2;
    const int tg  = lane & 3;
    const int rl  = lane & 15;
    const int kb  = (lane >> 4) * 4;

    const uint32_t etB = smb + OF_ET + h * 8192;   // ET for GEMM1, ND for GEMM2
    const uint32_t xnB = smb + OF_XN + h * 8192;
    const uint32_t wtB = smb + OF_WT;

    uint32_t adrA[2], adrBx[2], adrBw[2];
#pragma unroll
    for (int mt = 0; mt < 2; mt++) adrA[mt]  = etB + swzb(i0w + 16*mt + rl, kb);
#pragma unroll
    for (int hh = 0; hh < 2; hh++) {
        adrBx[hh] = xnB + swzb(j0w + 16*hh + rl, kb);
        adrBw[hh] = wtB + swzb(j0w + 16*hh + rl, kb);
    }

    uint32_t* ETt = ET + h * 2048;
    uint32_t* XNt = XN + h * 2048;

    for (int it = blockIdx.x; it < nPairs; it += gridDim.x) {
        BAR_HALF(h);   // prior iteration's GEMM2 reads of ET-region & Si done

        // ---- Phase A: X -> E^T, Xn^T packed + colsum partials ----
        const float* Xb = X + ((size_t)(2 * it + h)) * 4096u;
        float pc[8];
#pragma unroll
        for (int q = 0; q < 8; q++) pc[q] = 0.f;

#pragma unroll
        for (int p = 0; p < 2; p++) {
            const int R = 16*p + (wt >> 3);    // row-pair 0..31
            float x0[8], x1[8];
            float4 v;
            v = *(const float4*)(Xb + (2*R)*64      + 4*C); x0[0]=v.x; x0[1]=v.y; x0[2]=v.z; x0[3]=v.w;
            v = *(const float4*)(Xb + (2*R)*64 + 32 + 4*C); x0[4]=v.x; x0[5]=v.y; x0[6]=v.z; x0[7]=v.w;
            v = *(const float4*)(Xb + (2*R+1)*64    + 4*C); x1[0]=v.x; x1[1]=v.y; x1[2]=v.z; x1[3]=v.w;
            v = *(const float4*)(Xb + (2*R+1)*64+32 + 4*C); x1[4]=v.x; x1[5]=v.y; x1[6]=v.z; x1[7]=v.w;

            float s0=0.f, ss0=0.f, s1=0.f, ss1=0.f;
#pragma unroll
            for (int q = 0; q < 8; q++) {
                s0 += x0[q]; ss0 += x0[q]*x0[q];
                s1 += x1[q]; ss1 += x1[q]*x1[q];
            }
#pragma unroll
            for (int m = 1; m <= 4; m <<= 1) {   // 8 lanes share a row-pair
                s0  += __shfl_xor_sync(0xFFFFFFFFu, s0,  m);
                ss0 += __shfl_xor_sync(0xFFFFFFFFu, ss0, m);
                s1  += __shfl_xor_sync(0xFFFFFFFFu, s1,  m);
                ss1 += __shfl_xor_sync(0xFFFFFFFFu, ss1, m);
            }
            const float mean0 = s0 * (1.0f/64.0f);
            const float mean1 = s1 * (1.0f/64.0f);
            float var0 = fmaxf((ss0 - 64.0f*mean0*mean0) * (1.0f/63.0f), 0.0f);
            float var1 = fmaxf((ss1 - 64.0f*mean1*mean1) * (1.0f/63.0f), 0.0f);
            const float rv0 = 1.0f / (sqrtf(var0) + 1e-6f);
            const float rv1 = 1.0f / (sqrtf(var1) + 1e-6f);

#pragma unroll
            for (int q = 0; q < 8; q++) {
                const int c = 4*C + (q & 3) + (q >> 2) * 32;
                const float e0 = __expf(x0[q]);
                const float e1 = __expf(x1[q]);
                pc[q] += e0 + e1;
                ETt[swz(c, R)] = pack_h2(e0, e1);
                // FFMA-form LayerNorm: n = x*k + cc, k = a2*rv, cc = b2 - mean*k
                const float k0 = a2s[c] * rv0;
                const float k1 = a2s[c] * rv1;
                const float n0 = fmaf(x0[q], k0, fmaf(-mean0, k0, b2s[c]));
                const float n1 = fmaf(x1[q], k1, fmaf(-mean1, k1, b2s[c]));
                XNt[swz(c, R)] = pack_h2(n0, n1);
            }
        }
#pragma unroll
        for (int q = 0; q < 8; q++) {
            pc[q] += __shfl_xor_sync(0xFFFFFFFFu, pc[q], 8);
            pc[q] += __shfl_xor_sync(0xFFFFFFFFu, pc[q], 16);
        }
        if (lane < 8) {
#pragma unroll
            for (int q = 0; q < 8; q++) {
                const int c = 4*lane + (q & 3) + (q >> 2) * 32;
                Sp[h*256 + ww*64 + c] = pc[q];
            }
        }
        BAR_HALF(h);   // ET/XN/Sp visible

        // ---- Sinv (2 warps of the half, overlaps GEMM1 issue) ----
        if (wt < 64) {
            float s = Sp[h*256 + wt] + Sp[h*256 + 64 + wt]
                    + Sp[h*256 + 128 + wt] + Sp[h*256 + 192 + wt];
            Si[h*64 + wt] = 1.0f / s;
        }

        // ---- GEMM1: node_u = E^T @ Xn (UNSCALED) ----
        float acc[2][4][4];
#pragma unroll
        for (int mt = 0; mt < 2; mt++)
#pragma unroll
            for (int nt = 0; nt < 4; nt++)
#pragma unroll
                for (int e = 0; e < 4; e++) acc[mt][nt][e] = 0.f;

#pragma unroll
        for (int s = 0; s < 4; s++) {
            const uint32_t ax = (uint32_t)(s << 5);   // 8 k-pairs = 32B per step
            uint32_t a[2][4];
#pragma unroll
            for (int mt = 0; mt < 2; mt++)
                ldm_x4(a[mt][0], a[mt][1], a[mt][2], a[mt][3], adrA[mt] ^ ax);
#pragma unroll
            for (int hh = 0; hh < 2; hh++) {
                uint32_t b00, b01, b10, b11;
                ldm_x4(b00, b01, b10, b11, adrBx[hh] ^ ax);
                mma_f16(acc[0][2*hh],     a[0], b00, b10);
                mma_f16(acc[1][2*hh],     a[1], b00, b10);
                mma_f16(acc[0][2*hh + 1], a[0], b01, b11);
                mma_f16(acc[1][2*hh + 1], a[1], b01, b11);
            }
        }

        BAR_HALF(h);   // half done reading ET (and Si written) -> overlay ND

        // pack node_u -> ND (no scaling; Sinv deferred past relu)
#pragma unroll
        for (int mt = 0; mt < 2; mt++) {
            const int i = i0w + 16*mt + g;
#pragma unroll
            for (int nt = 0; nt < 4; nt++) {
                const int jp = (j0w >> 1) + 4*nt + tg;
                ET[h*2048 + swz(i,     jp)] = pack_h2(acc[mt][nt][0], acc[mt][nt][1]);
                ET[h*2048 + swz(i + 8, jp)] = pack_h2(acc[mt][nt][2], acc[mt][nt][3]);
            }
        }
        BAR_HALF(h);

        // ---- GEMM2: y = node_u @ W ----
#pragma unroll
        for (int mt = 0; mt < 2; mt++)
#pragma unroll
            for (int nt = 0; nt < 4; nt++)
#pragma unroll
                for (int e = 0; e < 4; e++) acc[mt][nt][e] = 0.f;

#pragma unroll
        for (int s = 0; s < 4; s++) {
            const uint32_t ax = (uint32_t)(s << 5);
            uint32_t a[2][4];
#pragma unroll
            for (int mt = 0; mt < 2; mt++)
                ldm_x4(a[mt][0], a[mt][1], a[mt][2], a[mt][3], adrA[mt] ^ ax);
#pragma unroll
            for (int hh = 0; hh < 2; hh++) {
                uint32_t b00, b01, b10, b11;
                ldm_x4(b00, b01, b10, b11, adrBw[hh] ^ ax);
                mma_f16(acc[0][2*hh],     a[0], b00, b10);
                mma_f16(acc[1][2*hh],     a[1], b00, b10);
                mma_f16(acc[0][2*hh + 1], a[0], b01, b11);
                mma_f16(acc[1][2*hh + 1], a[1], b01, b11);
            }
        }

        // out = Sinv[i] * relu(y)  (Si visible since post-GEMM1 barrier)
        float* Ob = out + ((size_t)(2 * it + h)) * 4096u;
#pragma unroll
        for (int mt = 0; mt < 2; mt++) {
            const int i = i0w + 16*mt + g;
            const float siA = Si[h*64 + i];
            const float siB = Si[h*64 + i + 8];
#pragma unroll
            for (int nt = 0; nt < 4; nt++) {
                const int j = j0w + 8*nt + 2*tg;
                float2 lo, hi;
                lo.x = fmaxf(acc[mt][nt][0], 0.f) * siA;
                lo.y = fmaxf(acc[mt][nt][1], 0.f) * siA;
                hi.x = fmaxf(acc[mt][nt][2], 0.f) * siB;
                hi.y = fmaxf(acc[mt][nt][3], 0.f) * siB;
                *(float2*)(Ob + i*64 + j)     = lo;
                *(float2*)(Ob + (i+8)*64 + j) = hi;
            }
        }
    }
}

extern "C" void kernel_launch(void* const* d_in, const int* in_sizes, int n_in,
                              void* d_out, int out_size) {
    const float* X  = (const float*)d_in[0];
    const float* W  = (const float*)d_in[1];
    const float* a2 = (const float*)d_in[2];
    const float* b2 = (const float*)d_in[3];
    float* out = (float*)d_out;

    const int nc = in_sizes[0] / 4096;   // 4096 batch tiles of 64x64
    const int nPairs = nc / 2;
    int grid = 148 * 4;
    if (grid > nPairs) grid = nPairs;
    cudaFuncSetAttribute(gnn_fused_kernel, cudaFuncAttributeMaxDynamicSharedMemorySize, SMEM_BYTES);
    gnn_fused_kernel<<<grid, 256, SMEM_BYTES>>>(X, W, a2, b2, out, nPairs);
}